// round 1
// baseline (speedup 1.0000x reference)
#include <cuda_runtime.h>

// ResidualStreamMapping: fused RMSNorm-scale + skinny GEMM (D=4096 -> 16) + Sinkhorn(20)
//
// Inputs (metadata order): x [B*T*4096] f32, W [16*4096] f32, bias [16] f32, alpha [1] f32
// Output: [B*T*16] f32
//
// Key identity: dot(x_norm, W[j]) = rsqrt(mean(x^2)+eps) * dot(x, W[j])
// -> single pass over x computing sumsq + 16 dot products simultaneously.

#define D        4096
#define KC       128                 // d-chunk per mainloop iteration (32 floats/lane -> 1 float4/lane)
#define NCHUNK   (D / KC)            // 32
#define NJ       16                  // output dots per row (n_streams^2)
#define RPW      4                   // rows per warp (register-tiled)
#define WPB      4                   // warps per block
#define ROWS_PB  (RPW * WPB)         // 16 rows per block

__global__ void __launch_bounds__(WPB * 32)
rsm_kernel(const float* __restrict__ x, const float* __restrict__ W,
           const float* __restrict__ bias, const float* __restrict__ alpha,
           float* __restrict__ out)
{
    __shared__ float ws[2][NJ][KC];   // double-buffered W chunk: 2 * 16 * 128 * 4B = 16 KB

    const int tid  = threadIdx.x;
    const int lane = tid & 31;
    const int warp = tid >> 5;

    const long long rowbase = (long long)blockIdx.x * ROWS_PB + (long long)warp * RPW;
    const float* xbase = x + rowbase * D;

    float acc[RPW][NJ];
    float ssq[RPW];
#pragma unroll
    for (int r = 0; r < RPW; ++r) {
        ssq[r] = 0.0f;
#pragma unroll
        for (int j = 0; j < NJ; ++j) acc[r][j] = 0.0f;
    }

    // ---- preload W chunk 0 into ws[0] ----
#pragma unroll
    for (int i = 0; i < 4; ++i) {
        int idx = tid + i * 128;          // 0..511 ; 512 float4 = 16 rows * 32 float4
        int j   = idx >> 5;
        int c4  = idx & 31;
        float4 v = *(const float4*)(W + (long long)j * D + c4 * 4);
        *(float4*)&ws[0][j][c4 * 4] = v;
    }
    __syncthreads();

    // ---- mainloop over D in 32 chunks of 128 ----
    for (int c = 0; c < NCHUNK; ++c) {
        const int buf = c & 1;

        // prefetch next W chunk into registers (LDG early, STS after compute)
        float4 wpre[4];
        if (c + 1 < NCHUNK) {
#pragma unroll
            for (int i = 0; i < 4; ++i) {
                int idx = tid + i * 128;
                int j   = idx >> 5;
                int c4  = idx & 31;
                wpre[i] = *(const float4*)(W + (long long)j * D + (c + 1) * KC + c4 * 4);
            }
        }

        // load x: 1 float4 per lane per row (coalesced 512B per row per warp)
        float4 xv[RPW];
#pragma unroll
        for (int r = 0; r < RPW; ++r)
            xv[r] = *(const float4*)(xbase + (long long)r * D + c * KC + lane * 4);

        // fused sum of squares
#pragma unroll
        for (int r = 0; r < RPW; ++r) {
            ssq[r] = fmaf(xv[r].x, xv[r].x, ssq[r]);
            ssq[r] = fmaf(xv[r].y, xv[r].y, ssq[r]);
            ssq[r] = fmaf(xv[r].z, xv[r].z, ssq[r]);
            ssq[r] = fmaf(xv[r].w, xv[r].w, ssq[r]);
        }

        // 16 dots x 4 rows: W float4 from smem reused across 4 rows
#pragma unroll
        for (int j = 0; j < NJ; ++j) {
            float4 wv = *(const float4*)&ws[buf][j][lane * 4];
#pragma unroll
            for (int r = 0; r < RPW; ++r) {
                acc[r][j] = fmaf(xv[r].x, wv.x, acc[r][j]);
                acc[r][j] = fmaf(xv[r].y, wv.y, acc[r][j]);
                acc[r][j] = fmaf(xv[r].z, wv.z, acc[r][j]);
                acc[r][j] = fmaf(xv[r].w, wv.w, acc[r][j]);
            }
        }

        // stage prefetched W into the other buffer
        if (c + 1 < NCHUNK) {
#pragma unroll
            for (int i = 0; i < 4; ++i) {
                int idx = tid + i * 128;
                int j   = idx >> 5;
                int c4  = idx & 31;
                *(float4*)&ws[buf ^ 1][j][c4 * 4] = wpre[i];
            }
        }
        __syncthreads();
    }

    // ---- warp butterfly reduction over the d-split (lanes) : 68 values ----
#pragma unroll
    for (int off = 16; off > 0; off >>= 1) {
#pragma unroll
        for (int r = 0; r < RPW; ++r) {
            ssq[r] += __shfl_xor_sync(0xffffffffu, ssq[r], off);
#pragma unroll
            for (int j = 0; j < NJ; ++j)
                acc[r][j] += __shfl_xor_sync(0xffffffffu, acc[r][j], off);
        }
    }
    // now every lane holds the full sums for all 4 rows

    // ---- epilogue: H = alpha * scale * dot + bias ; Sinkhorn(20) ----
    // lane l = g*16 + e ; handles matrix entry e of rows (g) and (g+2)
    const float alphav = *alpha;
    const int g = lane >> 4;
    const int e = lane & 15;
    const float be = bias[e];   // bias is [4,4] row-major

    float Mv[2];
#pragma unroll
    for (int h = 0; h < 2; ++h) {
        const int m = g + 2 * h;          // which of this warp's 4 rows
        float av = 0.0f, sv = 0.0f;
#pragma unroll
        for (int r = 0; r < RPW; ++r) {
            if (r == m) sv = ssq[r];
#pragma unroll
            for (int j = 0; j < NJ; ++j)
                if (r == m && j == e) av = acc[r][j];
        }
        const float scale = rsqrtf(sv * (1.0f / (float)D) + 1.1920929e-07f);
        const float H = fmaf(alphav * scale, av, be);
        Mv[h] = __expf(H);
    }

    // Sinkhorn: e = i*4 + j. col-sum over i -> xor {4,8}; row-sum over j -> xor {1,2}
#pragma unroll 4
    for (int it = 0; it < 20; ++it) {
#pragma unroll
        for (int h = 0; h < 2; ++h) {
            float cs = Mv[h];
            cs += __shfl_xor_sync(0xffffffffu, cs, 4);
            cs += __shfl_xor_sync(0xffffffffu, cs, 8);
            Mv[h] = __fdividef(Mv[h], cs + 1e-8f);
        }
#pragma unroll
        for (int h = 0; h < 2; ++h) {
            float rs = Mv[h];
            rs += __shfl_xor_sync(0xffffffffu, rs, 1);
            rs += __shfl_xor_sync(0xffffffffu, rs, 2);
            Mv[h] = __fdividef(Mv[h], rs + 1e-8f);
        }
    }

#pragma unroll
    for (int h = 0; h < 2; ++h) {
        const long long row = rowbase + (long long)(g + 2 * h);
        out[row * NJ + e] = Mv[h];
    }
}

extern "C" void kernel_launch(void* const* d_in, const int* in_sizes, int n_in,
                              void* d_out, int out_size)
{
    const float* x     = (const float*)d_in[0];
    const float* W     = (const float*)d_in[1];
    const float* bias  = (const float*)d_in[2];
    const float* alpha = (const float*)d_in[3];
    float* out = (float*)d_out;

    const int rows = in_sizes[0] / D;          // B*T = 16384
    const int grid = rows / ROWS_PB;           // 1024 blocks
    rsm_kernel<<<grid, WPB * 32>>>(x, W, bias, alpha, out);
}

// round 2
// speedup vs baseline: 1.1461x; 1.1461x over previous
#include <cuda_runtime.h>

// ResidualStreamMapping: fused RMSNorm-scale + skinny GEMM (D=4096 -> 16) + Sinkhorn(20)
//
// Round 2: f32x2 packed FMA (pair over j), transposed+swizzled W in smem via
// cp.async 3-stage pipeline, alpha folded into pre-transposed Wt, 8-warp blocks.

#define D        4096
#define KC       128
#define NCHUNK   (D / KC)            // 32
#define NJ       16
#define RPW      4                   // rows per warp
#define WPB      8                   // warps per block
#define THREADS  (WPB * 32)          // 256
#define ROWS_PB  (RPW * WPB)         // 32
#define STAGES   3
#define CHUNK_FLOATS (KC * NJ)       // 2048 floats = 8KB

typedef unsigned long long ull;

// W transposed [d][j], pre-scaled by alpha. 256 KB scratch (allowed: __device__ global).
__device__ __align__(16) float Wt[D * NJ];

// ---------- packed f32x2 helpers ----------
__device__ __forceinline__ ull dup2(float v) {
    ull r; asm("mov.b64 %0, {%1, %1};" : "=l"(r) : "f"(v)); return r;
}
__device__ __forceinline__ void fma2(ull& c, ull a, ull b) {
    asm("fma.rn.f32x2 %0, %1, %2, %0;" : "+l"(c) : "l"(a), "l"(b));
}
__device__ __forceinline__ ull add2(ull a, ull b) {
    ull r; asm("add.rn.f32x2 %0, %1, %2;" : "=l"(r) : "l"(a), "l"(b)); return r;
}
__device__ __forceinline__ float2 unpk(ull v) {
    float2 f; asm("mov.b64 {%0, %1}, %2;" : "=f"(f.x), "=f"(f.y) : "l"(v)); return f;
}

// ---------- prep: Wt[d][j] = alpha * W[j][d] ----------
__global__ void prep_kernel(const float* __restrict__ W, const float* __restrict__ alpha) {
    const float a = *alpha;
    int idx = blockIdx.x * blockDim.x + threadIdx.x;   // idx = j*D + d  (coalesced read)
    int j = idx >> 12;           // / 4096
    int d = idx & (D - 1);
    Wt[d * NJ + j] = a * W[idx];
}

// ---------- main kernel ----------
__global__ void __launch_bounds__(THREADS, 2)
rsm_kernel(const float* __restrict__ x, const float* __restrict__ bias,
           float* __restrict__ out)
{
    __shared__ __align__(16) float ws[STAGES][CHUNK_FLOATS];   // 3 * 8KB

    const int tid  = threadIdx.x;
    const int lane = tid & 31;
    const int warp = tid >> 5;

    const unsigned smem_base = (unsigned)__cvta_generic_to_shared(&ws[0][0]);

    // cp.async mapping: 512 groups of 16B per chunk; thread t owns groups t, t+256.
    // group g -> dl = g>>2, j4 = g&3 ; src offset dl*16 + j4*4 floats (contiguous in t)
    // dst offset = (dl>>1)*128 + ((((dl&1)<<2)|j4) ^ ((dl>>2)&7))*16
    unsigned dsto[2];
    int      srco[2];
#pragma unroll
    for (int i = 0; i < 2; ++i) {
        int g  = tid + i * THREADS;
        int dl = g >> 2, j4 = g & 3;
        int slot = (((dl & 1) << 2) | j4) ^ ((dl >> 2) & 7);
        dsto[i] = (unsigned)((dl >> 1) * 128 + slot * 16);
        srco[i] = dl * NJ + j4 * 4;
    }

    // prologue: issue W chunks 0 and 1
#pragma unroll
    for (int c0 = 0; c0 < 2; ++c0) {
#pragma unroll
        for (int i = 0; i < 2; ++i) {
            unsigned dst = smem_base + (unsigned)(c0 * CHUNK_FLOATS * 4) + dsto[i];
            const float* src = Wt + c0 * CHUNK_FLOATS + srco[i];
            asm volatile("cp.async.cg.shared.global [%0], [%1], 16;" :: "r"(dst), "l"(src));
        }
        asm volatile("cp.async.commit_group;");
    }

    const long long rowbase = (long long)blockIdx.x * ROWS_PB + (long long)warp * RPW;
    const float* xb = x + rowbase * D + lane * 4;

    ull acc[RPW][8];      // acc[r][jp] packs (j=2jp, j=2jp+1) partial sums over this lane's d-slice
    ull ssq[RPW];         // packed 2-way partial sum of squares
#pragma unroll
    for (int r = 0; r < RPW; ++r) {
        ssq[r] = 0ull;
#pragma unroll
        for (int jp = 0; jp < 8; ++jp) acc[r][jp] = 0ull;
    }

    const unsigned rowb_base = lane * 256u;   // (dl>>1)*128 for dl=4*lane
    const int swz = lane & 7;

    for (int c = 0; c < NCHUNK; ++c) {
        asm volatile("cp.async.wait_group 1;" ::: "memory");
        __syncthreads();

        // prefetch W chunk c+2 into stage (c+2)%3 (freed by the barrier above)
        if (c + 2 < NCHUNK) {
            unsigned sdst = smem_base + (unsigned)(((c + 2) % STAGES) * CHUNK_FLOATS * 4);
            const float* ssrc = Wt + (c + 2) * CHUNK_FLOATS;
#pragma unroll
            for (int i = 0; i < 2; ++i)
                asm volatile("cp.async.cg.shared.global [%0], [%1], 16;"
                             :: "r"(sdst + dsto[i]), "l"(ssrc + srco[i]));
        }
        asm volatile("cp.async.commit_group;");

        // x: one float4 (= ulonglong2, two f32x2) per row
        ulonglong2 xv[RPW];
        const float* xc = xb + c * KC;
#pragma unroll
        for (int r = 0; r < RPW; ++r)
            xv[r] = *(const ulonglong2*)(xc + (long long)r * D);

        // fused sum of squares (packed)
#pragma unroll
        for (int r = 0; r < RPW; ++r) {
            fma2(ssq[r], xv[r].x, xv[r].x);
            fma2(ssq[r], xv[r].y, xv[r].y);
        }

        const unsigned sb = smem_base + (unsigned)((c % STAGES) * CHUNK_FLOATS * 4);
        const unsigned rowb = sb + rowb_base;

#pragma unroll
        for (int dd = 0; dd < 4; ++dd) {
            // duplicate this d's x value into both packed halves, per row
            float2 xp0 = unpk(xv[0].x), xp0b = unpk(xv[0].y);
            ull a[RPW];
#pragma unroll
            for (int r = 0; r < RPW; ++r) {
                float2 p = (dd < 2) ? unpk(xv[r].x) : unpk(xv[r].y);
                float s  = (dd & 1) ? p.y : p.x;
                a[r] = dup2(s);
            }
            (void)xp0; (void)xp0b;

            const unsigned rofs = rowb + (unsigned)((dd >> 1) * 128);
            const int hi = (dd & 1) << 2;
#pragma unroll
            for (int j4 = 0; j4 < 4; ++j4) {
                unsigned adr = rofs + (unsigned)(((hi | j4) ^ swz) * 16);
                ull w01, w23;
                asm volatile("ld.shared.v2.b64 {%0, %1}, [%2];"
                             : "=l"(w01), "=l"(w23) : "r"(adr));
#pragma unroll
                for (int r = 0; r < RPW; ++r) {
                    fma2(acc[r][j4 * 2 + 0], a[r], w01);
                    fma2(acc[r][j4 * 2 + 1], a[r], w23);
                }
            }
        }
    }

    // ---- butterfly reduction over the 32-lane d-split (36 packed values) ----
#pragma unroll
    for (int off = 16; off > 0; off >>= 1) {
#pragma unroll
        for (int r = 0; r < RPW; ++r) {
            ssq[r] = add2(ssq[r], __shfl_xor_sync(0xffffffffu, ssq[r], off));
#pragma unroll
            for (int jp = 0; jp < 8; ++jp)
                acc[r][jp] = add2(acc[r][jp], __shfl_xor_sync(0xffffffffu, acc[r][jp], off));
        }
    }

    float sv_tot[RPW];
#pragma unroll
    for (int r = 0; r < RPW; ++r) {
        float2 p = unpk(ssq[r]);
        sv_tot[r] = p.x + p.y;
    }

    // ---- epilogue: H = scale * (alpha-folded dot) + bias ; Sinkhorn(20) ----
    const int g = lane >> 4;
    const int e = lane & 15;
    const float be = bias[e];

    float Mv[2];
#pragma unroll
    for (int h = 0; h < 2; ++h) {
        const int m = g + 2 * h;
        float sv = 0.0f, av = 0.0f;
#pragma unroll
        for (int r = 0; r < RPW; ++r) {
            if (r == m) {
                sv = sv_tot[r];
#pragma unroll
                for (int jp = 0; jp < 8; ++jp) {
                    if (jp == (e >> 1)) {
                        float2 p = unpk(acc[r][jp]);
                        av = (e & 1) ? p.y : p.x;
                    }
                }
            }
        }
        const float scale = rsqrtf(sv * (1.0f / (float)D) + 1.1920929e-07f);
        const float H = fmaf(scale, av, be);
        Mv[h] = __expf(H);
    }

    // Sinkhorn: e = i*4 + j. col-sum over i -> xor {4,8}; row-sum over j -> xor {1,2}
#pragma unroll 4
    for (int it = 0; it < 20; ++it) {
#pragma unroll
        for (int h = 0; h < 2; ++h) {
            float cs = Mv[h];
            cs += __shfl_xor_sync(0xffffffffu, cs, 4);
            cs += __shfl_xor_sync(0xffffffffu, cs, 8);
            Mv[h] = __fdividef(Mv[h], cs + 1e-8f);
        }
#pragma unroll
        for (int h = 0; h < 2; ++h) {
            float rs = Mv[h];
            rs += __shfl_xor_sync(0xffffffffu, rs, 1);
            rs += __shfl_xor_sync(0xffffffffu, rs, 2);
            Mv[h] = __fdividef(Mv[h], rs + 1e-8f);
        }
    }

#pragma unroll
    for (int h = 0; h < 2; ++h) {
        const long long row = rowbase + (long long)(g + 2 * h);
        out[row * NJ + e] = Mv[h];
    }
}

extern "C" void kernel_launch(void* const* d_in, const int* in_sizes, int n_in,
                              void* d_out, int out_size)
{
    const float* x     = (const float*)d_in[0];
    const float* W     = (const float*)d_in[1];
    const float* bias  = (const float*)d_in[2];
    const float* alpha = (const float*)d_in[3];
    float* out = (float*)d_out;

    // prep: transpose + alpha-fold W  (65536 elements)
    prep_kernel<<<(NJ * D) / 256, 256>>>(W, alpha);

    const int rows = in_sizes[0] / D;          // B*T
    const int grid = rows / ROWS_PB;
    rsm_kernel<<<grid, THREADS>>>(x, bias, out);
}

// round 3
// speedup vs baseline: 1.1797x; 1.0293x over previous
#include <cuda_runtime.h>

// ResidualStreamMapping: fused RMSNorm-scale + skinny GEMM (D=4096 -> 16) + Sinkhorn(20)
//
// Round 3: x streamed via cp.async (fixes the x-LDG MLP cap that held HBM at 2.65TB/s),
// W + x share a 3-stage smem pipeline; f32x2 packed FMA; alpha folded into Wt.

#define D        4096
#define KC       128
#define NCHUNK   (D / KC)            // 32
#define NJ       16
#define RPW      4                   // rows per warp
#define WPB      8                   // warps per block
#define THREADS  (WPB * 32)          // 256
#define ROWS_PB  (RPW * WPB)         // 32
#define STAGES   3
#define CHUNK_FLOATS (KC * NJ)       // 2048 floats = 8KB W per chunk

#define WBYTES   (CHUNK_FLOATS * 4)          // 8192
#define XBYTES   (ROWS_PB * KC * 4)          // 16384
#define STAGE_B  (WBYTES + XBYTES)           // 24576
#define SMEM_B   (STAGES * STAGE_B)          // 73728

typedef unsigned long long ull;

// W transposed [d][j], pre-scaled by alpha. 256 KB scratch (__device__ global: allowed).
__device__ __align__(16) float Wt[D * NJ];

// ---------- packed f32x2 helpers ----------
__device__ __forceinline__ ull dup2(float v) {
    ull r; asm("mov.b64 %0, {%1, %1};" : "=l"(r) : "f"(v)); return r;
}
__device__ __forceinline__ void fma2(ull& c, ull a, ull b) {
    asm("fma.rn.f32x2 %0, %1, %2, %0;" : "+l"(c) : "l"(a), "l"(b));
}
__device__ __forceinline__ ull add2(ull a, ull b) {
    ull r; asm("add.rn.f32x2 %0, %1, %2;" : "=l"(r) : "l"(a), "l"(b)); return r;
}
__device__ __forceinline__ float2 unpk(ull v) {
    float2 f; asm("mov.b64 {%0, %1}, %2;" : "=f"(f.x), "=f"(f.y) : "l"(v)); return f;
}
__device__ __forceinline__ void cpa16(unsigned dst, const float* src) {
    asm volatile("cp.async.cg.shared.global [%0], [%1], 16;" :: "r"(dst), "l"(src));
}

// ---------- prep: Wt[d][j] = alpha * W[j][d] ----------
__global__ void prep_kernel(const float* __restrict__ W, const float* __restrict__ alpha) {
    const float a = *alpha;
    int idx = blockIdx.x * blockDim.x + threadIdx.x;   // idx = j*D + d (coalesced read)
    int j = idx >> 12;
    int d = idx & (D - 1);
    Wt[d * NJ + j] = a * W[idx];
}

// ---------- main kernel ----------
__global__ void __launch_bounds__(THREADS, 2)
rsm_kernel(const float* __restrict__ x, const float* __restrict__ bias,
           float* __restrict__ out)
{
    extern __shared__ __align__(16) unsigned char sm[];
    const unsigned smem_base = (unsigned)__cvta_generic_to_shared(sm);

    const int tid  = threadIdx.x;
    const int lane = tid & 31;
    const int warp = tid >> 5;

    const long long blockrow = (long long)blockIdx.x * ROWS_PB;
    const long long rowbase  = blockrow + (long long)warp * RPW;

    // ---- cp.async source/dest offsets ----
    // W: 512 16B-groups/chunk; thread owns groups tid, tid+256.
    //    group g -> dl=g>>2, j4=g&3 ; swizzled dst slot for conflict-free LDS.
    unsigned wdst[2];
    int      wsrc[2];
#pragma unroll
    for (int i = 0; i < 2; ++i) {
        int g  = tid + i * THREADS;
        int dl = g >> 2, j4 = g & 3;
        int slot = (((dl & 1) << 2) | j4) ^ ((dl >> 2) & 7);
        wdst[i] = (unsigned)((dl >> 1) * 128 + slot * 16);
        wsrc[i] = dl * NJ + j4 * 4;
    }
    // x: 1024 16B-groups/chunk (32 rows x 32 float4); thread owns g = tid + i*256, i<4.
    //    linear layout xs[row][KC]: dst byte = g*16 ; src = x[blockrow + (g>>5)][(g&31)*4 + c*KC]
    const float* xsrc[4];
    unsigned     xdst[4];
#pragma unroll
    for (int i = 0; i < 4; ++i) {
        int g = tid + i * THREADS;
        xsrc[i] = x + (blockrow + (long long)(g >> 5)) * D + (g & 31) * 4;
        xdst[i] = (unsigned)(WBYTES + g * 16);
    }

    // ---- prologue: issue chunks 0 and 1 ----
#pragma unroll
    for (int c0 = 0; c0 < 2; ++c0) {
        const unsigned sb = smem_base + (unsigned)(c0 * STAGE_B);
        const float* wsb = Wt + c0 * CHUNK_FLOATS;
#pragma unroll
        for (int i = 0; i < 2; ++i) cpa16(sb + wdst[i], wsb + wsrc[i]);
#pragma unroll
        for (int i = 0; i < 4; ++i) cpa16(sb + xdst[i], xsrc[i] + c0 * KC);
        asm volatile("cp.async.commit_group;");
    }

    ull acc[RPW][8];   // acc[r][jp] packs (j=2jp, 2jp+1), partials over this lane's d-slice
    ull ssq[RPW];
#pragma unroll
    for (int r = 0; r < RPW; ++r) {
        ssq[r] = 0ull;
#pragma unroll
        for (int jp = 0; jp < 8; ++jp) acc[r][jp] = 0ull;
    }

    const unsigned wrow_base = lane * 256u;    // (dl>>1)*128 for dl=4*lane
    const unsigned xrow_base = (unsigned)(WBYTES + warp * RPW * KC * 4 + lane * 16);
    const int swz = lane & 7;

    for (int c = 0; c < NCHUNK; ++c) {
        asm volatile("cp.async.wait_group 1;" ::: "memory");
        __syncthreads();

        // issue chunk c+2 into stage (c+2)%3 (== (c-1)%3, freed by the barrier)
        if (c + 2 < NCHUNK) {
            const unsigned sb = smem_base + (unsigned)(((c + 2) % STAGES) * STAGE_B);
            const float* wsb = Wt + (c + 2) * CHUNK_FLOATS;
#pragma unroll
            for (int i = 0; i < 2; ++i) cpa16(sb + wdst[i], wsb + wsrc[i]);
#pragma unroll
            for (int i = 0; i < 4; ++i) cpa16(sb + xdst[i], xsrc[i] + (c + 2) * KC);
        }
        asm volatile("cp.async.commit_group;");

        const unsigned sb = smem_base + (unsigned)((c % STAGES) * STAGE_B);

        // x from smem: one LDS.128 per row (lanes contiguous 512B -> conflict-free)
        ulonglong2 xv[RPW];
#pragma unroll
        for (int r = 0; r < RPW; ++r) {
            unsigned adr = sb + xrow_base + (unsigned)(r * KC * 4);
            asm volatile("ld.shared.v2.b64 {%0, %1}, [%2];"
                         : "=l"(xv[r].x), "=l"(xv[r].y) : "r"(adr));
        }

        // fused sum of squares (packed)
#pragma unroll
        for (int r = 0; r < RPW; ++r) {
            fma2(ssq[r], xv[r].x, xv[r].x);
            fma2(ssq[r], xv[r].y, xv[r].y);
        }

        const unsigned rowb = sb + wrow_base;
#pragma unroll
        for (int dd = 0; dd < 4; ++dd) {
            ull a[RPW];
#pragma unroll
            for (int r = 0; r < RPW; ++r) {
                float2 p = (dd < 2) ? unpk(xv[r].x) : unpk(xv[r].y);
                a[r] = dup2((dd & 1) ? p.y : p.x);
            }
            const unsigned rofs = rowb + (unsigned)((dd >> 1) * 128);
            const int hi = (dd & 1) << 2;
#pragma unroll
            for (int j4 = 0; j4 < 4; ++j4) {
                unsigned adr = rofs + (unsigned)(((hi | j4) ^ swz) * 16);
                ull w01, w23;
                asm volatile("ld.shared.v2.b64 {%0, %1}, [%2];"
                             : "=l"(w01), "=l"(w23) : "r"(adr));
#pragma unroll
                for (int r = 0; r < RPW; ++r) {
                    fma2(acc[r][j4 * 2 + 0], a[r], w01);
                    fma2(acc[r][j4 * 2 + 1], a[r], w23);
                }
            }
        }
    }

    // ---- butterfly reduction over the 32-lane d-split ----
#pragma unroll
    for (int off = 16; off > 0; off >>= 1) {
#pragma unroll
        for (int r = 0; r < RPW; ++r) {
            ssq[r] = add2(ssq[r], __shfl_xor_sync(0xffffffffu, ssq[r], off));
#pragma unroll
            for (int jp = 0; jp < 8; ++jp)
                acc[r][jp] = add2(acc[r][jp], __shfl_xor_sync(0xffffffffu, acc[r][jp], off));
        }
    }

    float sv_tot[RPW];
#pragma unroll
    for (int r = 0; r < RPW; ++r) {
        float2 p = unpk(ssq[r]);
        sv_tot[r] = p.x + p.y;
    }

    // ---- epilogue: H = scale * (alpha-folded dot) + bias ; Sinkhorn(20) ----
    const int g = lane >> 4;
    const int e = lane & 15;
    const float be = bias[e];

    float Mv[2];
#pragma unroll
    for (int h = 0; h < 2; ++h) {
        const int m = g + 2 * h;
        float sv = 0.0f, av = 0.0f;
#pragma unroll
        for (int r = 0; r < RPW; ++r) {
            if (r == m) {
                sv = sv_tot[r];
#pragma unroll
                for (int jp = 0; jp < 8; ++jp) {
                    if (jp == (e >> 1)) {
                        float2 p = unpk(acc[r][jp]);
                        av = (e & 1) ? p.y : p.x;
                    }
                }
            }
        }
        const float scale = rsqrtf(sv * (1.0f / (float)D) + 1.1920929e-07f);
        const float H = fmaf(scale, av, be);
        Mv[h] = __expf(H);
    }

    // Sinkhorn: e = i*4 + j. col-sum over i -> xor {4,8}; row-sum over j -> xor {1,2}
#pragma unroll 4
    for (int it = 0; it < 20; ++it) {
#pragma unroll
        for (int h = 0; h < 2; ++h) {
            float cs = Mv[h];
            cs += __shfl_xor_sync(0xffffffffu, cs, 4);
            cs += __shfl_xor_sync(0xffffffffu, cs, 8);
            Mv[h] = __fdividef(Mv[h], cs + 1e-8f);
        }
#pragma unroll
        for (int h = 0; h < 2; ++h) {
            float rs = Mv[h];
            rs += __shfl_xor_sync(0xffffffffu, rs, 1);
            rs += __shfl_xor_sync(0xffffffffu, rs, 2);
            Mv[h] = __fdividef(Mv[h], rs + 1e-8f);
        }
    }

#pragma unroll
    for (int h = 0; h < 2; ++h) {
        const long long row = rowbase + (long long)(g + 2 * h);
        out[row * NJ + e] = Mv[h];
    }
}

extern "C" void kernel_launch(void* const* d_in, const int* in_sizes, int n_in,
                              void* d_out, int out_size)
{
    const float* x     = (const float*)d_in[0];
    const float* W     = (const float*)d_in[1];
    const float* bias  = (const float*)d_in[2];
    const float* alpha = (const float*)d_in[3];
    float* out = (float*)d_out;

    prep_kernel<<<(NJ * D) / 256, 256>>>(W, alpha);

    cudaFuncSetAttribute(rsm_kernel, cudaFuncAttributeMaxDynamicSharedMemorySize, SMEM_B);

    const int rows = in_sizes[0] / D;          // B*T
    const int grid = rows / ROWS_PB;
    rsm_kernel<<<grid, THREADS, SMEM_B>>>(x, bias, out);
}

// round 4
// speedup vs baseline: 1.3200x; 1.1190x over previous
#include <cuda_runtime.h>
#include <cuda_bf16.h>

// ResidualStreamMapping: fused RMSNorm-scale + skinny GEMM (D=4096 -> 16) + Sinkhorn(20)
//
// Round 4: W resident in smem (bf16, alpha-folded, swizzled, 128KB) loaded once;
// per-warp self-paced x pipeline via cp.async (NO barriers in mainloop -> no convoy);
// 512-thread blocks, 128 blocks, exactly 2 row-tiles per warp (perfect balance).

#define D        4096
#define NJ       16
#define KC       128
#define NCHUNK   32
#define RPW      4
#define WARPS    16
#define THREADS  512
#define NBLOCKS  128

#define XSTAGE_B 2048                     // 4 rows * 128 floats * 4B per warp-stage
#define XSTAGES  3
#define XWARP_B  (XSTAGES * XSTAGE_B)     // 6144
#define WB_OFF   (WARPS * XWARP_B)        // 98304
#define W_BYTES  (D * NJ * 2)             // 131072 (bf16)
#define SMEM_B   (WB_OFF + W_BYTES)       // 229376

typedef unsigned long long ull;

// alpha-folded, transposed W in bf16: Wt_bf[d*16 + j] = bf16(alpha * W[j][d])
__device__ __align__(16) __nv_bfloat16 Wt_bf[D * NJ];

// ---------- helpers ----------
__device__ __forceinline__ ull dup2(float v) {
    ull r; asm("mov.b64 %0, {%1, %1};" : "=l"(r) : "f"(v)); return r;
}
__device__ __forceinline__ void fma2(ull& c, ull a, ull b) {
    asm("fma.rn.f32x2 %0, %1, %2, %0;" : "+l"(c) : "l"(a), "l"(b));
}
__device__ __forceinline__ ull add2(ull a, ull b) {
    ull r; asm("add.rn.f32x2 %0, %1, %2;" : "=l"(r) : "l"(a), "l"(b)); return r;
}
__device__ __forceinline__ float2 unpk(ull v) {
    float2 f; asm("mov.b64 {%0, %1}, %2;" : "=f"(f.x), "=f"(f.y) : "l"(v)); return f;
}
// uint32 holding bf16 pair (j_even low, j_odd high) -> packed f32x2 (even in low)
__device__ __forceinline__ ull bf2f2(unsigned v) {
    unsigned lo = v << 16;
    unsigned hi = v & 0xffff0000u;
    ull r; asm("mov.b64 %0, {%1, %2};" : "=l"(r) : "r"(lo), "r"(hi));
    return r;
}
__device__ __forceinline__ void cpa16(unsigned dst, const void* src) {
    asm volatile("cp.async.cg.shared.global [%0], [%1], 16;" :: "r"(dst), "l"(src));
}

// ---------- prep: Wt_bf[d][j] = bf16(alpha * W[j][d]) ----------
__global__ void prep_kernel(const float* __restrict__ W, const float* __restrict__ alpha) {
    const float a = *alpha;
    int idx = blockIdx.x * blockDim.x + threadIdx.x;   // 0..65535, = j*D + d
    int j = idx >> 12;
    int d = idx & (D - 1);
    Wt_bf[d * NJ + j] = __float2bfloat16(a * W[idx]);
}

// ---------- main kernel ----------
__global__ void __launch_bounds__(THREADS, 1)
rsm_kernel(const float* __restrict__ x, const float* __restrict__ bias,
           float* __restrict__ out, int ntiles)
{
    extern __shared__ __align__(16) unsigned char sm[];
    const unsigned sbase = (unsigned)__cvta_generic_to_shared(sm);

    const int tid  = threadIdx.x;
    const int lane = tid & 31;
    const int warp = tid >> 5;
    const int wgid = blockIdx.x * WARPS + warp;        // 0..2047
    const int nwarps_total = NBLOCKS * WARPS;          // 2048
    const int nk = ntiles * NCHUNK;

    // ---- stage W into smem once (swizzled 16B units: u' = u ^ ((u>>3)&7)) ----
#pragma unroll
    for (int i = 0; i < (W_BYTES / 16) / THREADS; ++i) {
        unsigned u  = (unsigned)(tid + i * THREADS);
        unsigned up = u ^ ((u >> 3) & 7u);
        cpa16(sbase + WB_OFF + (up << 4), (const char*)Wt_bf + ((size_t)u << 4));
    }
    asm volatile("cp.async.commit_group;");

    const unsigned xw = sbase + (unsigned)(warp * XWARP_B) + (unsigned)(lane * 16);
    const float be = bias[lane & 15];                  // prefetch (hides gmem latency)

    // per-warp x issue: chunk k -> tile=k/32, c=k&31, stage=k%3
    auto issue_x = [&](int k) {
        int tile = k >> 5, c = k & 31;
        const float* s = x + ((long long)(wgid + tile * nwarps_total) * RPW) * D
                           + c * KC + lane * 4;
        unsigned dstb = xw + (unsigned)((k % XSTAGES) * XSTAGE_B);
#pragma unroll
        for (int r = 0; r < RPW; ++r)
            cpa16(dstb + (unsigned)(r * 512), s + (long long)r * D);
    };

    issue_x(0); asm volatile("cp.async.commit_group;");
    issue_x(1); asm volatile("cp.async.commit_group;");
    asm volatile("cp.async.wait_group 1;" ::: "memory");  // W + x0 complete
    __syncthreads();                                      // W visible to all (only barrier)

    // hoisted W addressing: unit index = c*256 + 8*lane + (2dd+h); swizzle = lane&7
    const unsigned wlane = sbase + WB_OFF + (unsigned)(lane << 7);   // (8*lane)<<4
    unsigned ofs[8];
#pragma unroll
    for (int t = 0; t < 8; ++t) ofs[t] = (unsigned)((t ^ (lane & 7)) << 4);

    int k = 0;
    for (int tile = 0; tile < ntiles; ++tile) {
        ull acc[RPW][8];
        ull ssq[RPW];
#pragma unroll
        for (int r = 0; r < RPW; ++r) {
            ssq[r] = 0ull;
#pragma unroll
            for (int jp = 0; jp < 8; ++jp) acc[r][jp] = 0ull;
        }

#pragma unroll 1
        for (int c = 0; c < NCHUNK; ++c, ++k) {
            if (k + 2 < nk) issue_x(k + 2);
            asm volatile("cp.async.commit_group;");
            asm volatile("cp.async.wait_group 2;" ::: "memory");  // x(k) ready

            // x: 4 LDS.128 from this warp's private buffer (conflict-free)
            const unsigned sx = xw + (unsigned)((k % XSTAGES) * XSTAGE_B);
            ulonglong2 xv[RPW];
#pragma unroll
            for (int r = 0; r < RPW; ++r)
                asm volatile("ld.shared.v2.b64 {%0, %1}, [%2];"
                             : "=l"(xv[r].x), "=l"(xv[r].y)
                             : "r"(sx + (unsigned)(r * 512)));

#pragma unroll
            for (int r = 0; r < RPW; ++r) {
                fma2(ssq[r], xv[r].x, xv[r].x);
                fma2(ssq[r], xv[r].y, xv[r].y);
            }

            const unsigned wck = wlane + (unsigned)(c << 12);   // + c*256 units
#pragma unroll
            for (int dd = 0; dd < 4; ++dd) {
                ull a[RPW];
#pragma unroll
                for (int r = 0; r < RPW; ++r) {
                    float2 p = (dd < 2) ? unpk(xv[r].x) : unpk(xv[r].y);
                    a[r] = dup2((dd & 1) ? p.y : p.x);
                }
                uint4 v0, v1;   // j-pairs 0..3 and 4..7 (bf16) for this d
                asm volatile("ld.shared.v4.b32 {%0, %1, %2, %3}, [%4];"
                             : "=r"(v0.x), "=r"(v0.y), "=r"(v0.z), "=r"(v0.w)
                             : "r"(wck + ofs[2 * dd]));
                asm volatile("ld.shared.v4.b32 {%0, %1, %2, %3}, [%4];"
                             : "=r"(v1.x), "=r"(v1.y), "=r"(v1.z), "=r"(v1.w)
                             : "r"(wck + ofs[2 * dd + 1]));
                unsigned wraw[8] = {v0.x, v0.y, v0.z, v0.w, v1.x, v1.y, v1.z, v1.w};
#pragma unroll
                for (int p = 0; p < 8; ++p) {
                    ull w = bf2f2(wraw[p]);
#pragma unroll
                    for (int r = 0; r < RPW; ++r)
                        fma2(acc[r][p], a[r], w);
                }
            }
        }

        // ---- butterfly reduction over the 32-lane d-split ----
#pragma unroll
        for (int off = 16; off > 0; off >>= 1) {
#pragma unroll
            for (int r = 0; r < RPW; ++r) {
                ssq[r] = add2(ssq[r], __shfl_xor_sync(0xffffffffu, ssq[r], off));
#pragma unroll
                for (int jp = 0; jp < 8; ++jp)
                    acc[r][jp] = add2(acc[r][jp], __shfl_xor_sync(0xffffffffu, acc[r][jp], off));
            }
        }

        float sv_tot[RPW];
#pragma unroll
        for (int r = 0; r < RPW; ++r) {
            float2 p = unpk(ssq[r]);
            sv_tot[r] = p.x + p.y;
        }

        // ---- epilogue: H = scale*(alpha-folded dot) + bias ; Sinkhorn(20) ----
        const int g = lane >> 4;
        const int e = lane & 15;

        float Mv[2];
#pragma unroll
        for (int h = 0; h < 2; ++h) {
            const int m = g + 2 * h;
            float sv = 0.0f, av = 0.0f;
#pragma unroll
            for (int r = 0; r < RPW; ++r) {
                if (r == m) {
                    sv = sv_tot[r];
#pragma unroll
                    for (int jp = 0; jp < 8; ++jp) {
                        if (jp == (e >> 1)) {
                            float2 p = unpk(acc[r][jp]);
                            av = (e & 1) ? p.y : p.x;
                        }
                    }
                }
            }
            const float scale = rsqrtf(sv * (1.0f / (float)D) + 1.1920929e-07f);
            const float H = fmaf(scale, av, be);
            Mv[h] = __expf(H);
        }

        // Sinkhorn: e = i*4 + j. col-sum over i -> xor {4,8}; row-sum over j -> xor {1,2}
#pragma unroll 4
        for (int it = 0; it < 20; ++it) {
#pragma unroll
            for (int h = 0; h < 2; ++h) {
                float cs = Mv[h];
                cs += __shfl_xor_sync(0xffffffffu, cs, 4);
                cs += __shfl_xor_sync(0xffffffffu, cs, 8);
                Mv[h] = __fdividef(Mv[h], cs + 1e-8f);
            }
#pragma unroll
            for (int h = 0; h < 2; ++h) {
                float rs = Mv[h];
                rs += __shfl_xor_sync(0xffffffffu, rs, 1);
                rs += __shfl_xor_sync(0xffffffffu, rs, 2);
                Mv[h] = __fdividef(Mv[h], rs + 1e-8f);
            }
        }

        const long long rowbase = (long long)(wgid + tile * nwarps_total) * RPW;
#pragma unroll
        for (int h = 0; h < 2; ++h) {
            const long long row = rowbase + (long long)(g + 2 * h);
            out[row * NJ + e] = Mv[h];
        }
    }
}

extern "C" void kernel_launch(void* const* d_in, const int* in_sizes, int n_in,
                              void* d_out, int out_size)
{
    const float* x     = (const float*)d_in[0];
    const float* W     = (const float*)d_in[1];
    const float* bias  = (const float*)d_in[2];
    const float* alpha = (const float*)d_in[3];
    float* out = (float*)d_out;

    prep_kernel<<<(NJ * D) / 256, 256>>>(W, alpha);

    static int configured = -1;
    cudaFuncSetAttribute(rsm_kernel, cudaFuncAttributeMaxDynamicSharedMemorySize, SMEM_B);
    (void)configured;

    const int rows   = in_sizes[0] / D;                        // B*T = 16384
    const int ntiles = rows / (NBLOCKS * WARPS * RPW);         // 2
    rsm_kernel<<<NBLOCKS, THREADS, SMEM_B>>>(x, bias, out, ntiles);
}

// round 6
// speedup vs baseline: 2.3594x; 1.7874x over previous
#include <cuda_runtime.h>
#include <cuda_bf16.h>
#include <cstdint>

// ResidualStreamMapping: RMSNorm-scale + skinny GEMM (D=4096 -> 16) + Sinkhorn(20)
//
// Round 6: GEMM on mma.sync.m16n8k16 bf16 (sm_80 PTX -> compiles at compute_100,
// runs on HMMA tensor pipe). Per-warp self-paced cp.async pipeline, zero block
// barriers in mainloop. B pre-packed into exact fragment layout by prep kernel.

#define D        4096
#define NJ       16
#define KCH      64                       // d per pipeline chunk
#define NCH      (D / KCH)                // 64
#define WARPS    8
#define THREADS  256
#define NBLOCKS  128                      // 1024 warps total = 16384 rows / 16

#define PITCHB   288                      // x row pitch in bytes (72 f32) - conflict-free
#define XSTG     (16 * PITCHB)            // 4608 per warp-stage
#define BSTG     2048                     // 64k x 16n bf16 fragments per chunk
#define NSTAGE   3
#define XWARP    (NSTAGE * XSTG)          // 13824
#define BWARP    (NSTAGE * BSTG)          // 6144
#define OFF_B    (WARPS * XWARP)          // 110592
#define SMEM_B   (OFF_B + WARPS * BWARP)  // 159744

typedef unsigned long long ull;

// B fragments: [kc16 0..255][lane 0..31][4 u32] ; u32 r in {t0b0,t0b1,t1b0,t1b1}
__device__ __align__(16) uint32_t Bfrag[256 * 32 * 4];   // 128 KB

// ---------- helpers ----------
__device__ __forceinline__ void fma2(ull& c, ull a, ull b) {
    asm("fma.rn.f32x2 %0, %1, %2, %0;" : "+l"(c) : "l"(a), "l"(b));
}
__device__ __forceinline__ float2 unpk(ull v) {
    float2 f; asm("mov.b64 {%0, %1}, %2;" : "=f"(f.x), "=f"(f.y) : "l"(v)); return f;
}
__device__ __forceinline__ void cpa16(unsigned dst, const void* src) {
    asm volatile("cp.async.cg.shared.global [%0], [%1], 16;" :: "r"(dst), "l"(src));
}
__device__ __forceinline__ ull lds64(unsigned a) {
    ull r; asm volatile("ld.shared.b64 %0, [%1];" : "=l"(r) : "r"(a)); return r;
}
__device__ __forceinline__ uint32_t cvt2(ull x) {   // f32 pair (lo=k, hi=k+1) -> bf16x2
    float2 p = unpk(x);
    uint32_t r; asm("cvt.rn.bf16x2.f32 %0, %1, %2;" : "=r"(r) : "f"(p.y), "f"(p.x));
    return r;
}
__device__ __forceinline__ void mma16816(float* c, const uint32_t* a,
                                         uint32_t b0, uint32_t b1) {
    asm volatile("mma.sync.aligned.m16n8k16.row.col.f32.bf16.bf16.f32 "
                 "{%0,%1,%2,%3}, {%4,%5,%6,%7}, {%8,%9}, {%0,%1,%2,%3};"
                 : "+f"(c[0]), "+f"(c[1]), "+f"(c[2]), "+f"(c[3])
                 : "r"(a[0]), "r"(a[1]), "r"(a[2]), "r"(a[3]), "r"(b0), "r"(b1));
}

// ---------- prep: pack alpha*W into per-lane m16n8k16 B fragments ----------
__global__ void prep_kernel(const float* __restrict__ W, const float* __restrict__ alpha) {
    const float a = *alpha;
    int t = blockIdx.x * blockDim.x + threadIdx.x;   // 0..32767
    int kc   = t >> 7;          // k16 chunk 0..255
    int rem  = t & 127;
    int lane = rem >> 2;
    int r    = rem & 3;
    int tl   = r >> 1;          // n-tile (0: n0-7, 1: n8-15)
    int half = r & 1;           // k half (0: k0-7, 1: k8-15)
    int n = (lane >> 2) + 8 * tl;
    int k = kc * 16 + (lane & 3) * 2 + 8 * half;
    float w0 = a * W[n * D + k];
    float w1 = a * W[n * D + k + 1];
    uint32_t packed;
    asm("cvt.rn.bf16x2.f32 %0, %1, %2;" : "=r"(packed) : "f"(w1), "f"(w0));
    Bfrag[t] = packed;          // byte offset = kc*512 + lane*16 + r*4
}

// ---------- main kernel ----------
__global__ void __launch_bounds__(THREADS, 1)
rsm_kernel(const float* __restrict__ x, const float* __restrict__ bias,
           float* __restrict__ out)
{
    extern __shared__ __align__(16) unsigned char sm[];
    const unsigned sb = (unsigned)__cvta_generic_to_shared(sm);

    const int tid  = threadIdx.x;
    const int lane = tid & 31;
    const int warp = tid >> 5;

    const long long row0 = ((long long)blockIdx.x * WARPS + warp) * 16;

    const unsigned xw = sb + (unsigned)(warp * XWARP);
    const unsigned bw = sb + (unsigned)(OFF_B + warp * BWARP);

    // per-warp chunk prefetch (x f32 tile + B fragment tile), fully self-paced
    auto prefetch = [&](int c) {
        const unsigned xs = xw + (unsigned)((c % NSTAGE) * XSTG);
#pragma unroll
        for (int i = 0; i < 8; ++i) {
            int g = lane + i * 32;              // 256 granules: 16 rows x 16
            int row = g >> 4, q = g & 15;
            cpa16(xs + (unsigned)(row * PITCHB + q * 16),
                  x + (row0 + row) * D + c * KCH + q * 4);
        }
        const unsigned bs = bw + (unsigned)((c % NSTAGE) * BSTG);
        const uint8_t* bsrc = (const uint8_t*)Bfrag + (size_t)c * BSTG;
#pragma unroll
        for (int i = 0; i < 4; ++i) {
            int g = lane + i * 32;
            cpa16(bs + (unsigned)(g * 16), bsrc + g * 16);
        }
    };

    prefetch(0); asm volatile("cp.async.commit_group;");
    prefetch(1); asm volatile("cp.async.commit_group;");

    // fragment addressing: r0 = lane>>2, i = lane&3
    const unsigned fr0 = xw + (unsigned)((lane >> 2) * PITCHB + (lane & 3) * 8);
    const unsigned fr8 = fr0 + 8 * PITCHB;
    const unsigned bfr = bw + (unsigned)(lane * 16);

    float acc[8];                 // 2 n8-tiles x 4
#pragma unroll
    for (int i = 0; i < 8; ++i) acc[i] = 0.0f;
    ull ssqa = 0ull, ssqb = 0ull; // rows r0 and r0+8

#pragma unroll 1
    for (int c = 0; c < NCH; ++c) {
        if (c + 2 < NCH) prefetch(c + 2);
        asm volatile("cp.async.commit_group;");
        asm volatile("cp.async.wait_group 2;" ::: "memory");   // chunk c arrived

        const unsigned st = (unsigned)((c % NSTAGE) * XSTG);
        const unsigned bt = (unsigned)((c % NSTAGE) * BSTG);

#pragma unroll
        for (int s = 0; s < 4; ++s) {                          // 4 k16 sub-chunks
            ull x0 = lds64(fr0 + st + s * 64);                 // (r0,   k0-7 pair)
            ull x1 = lds64(fr8 + st + s * 64);                 // (r0+8, k0-7 pair)
            ull x2 = lds64(fr0 + st + s * 64 + 32);            // (r0,   k8-15)
            ull x3 = lds64(fr8 + st + s * 64 + 32);            // (r0+8, k8-15)

            fma2(ssqa, x0, x0); fma2(ssqb, x1, x1);
            fma2(ssqa, x2, x2); fma2(ssqb, x3, x3);

            uint32_t a[4] = { cvt2(x0), cvt2(x1), cvt2(x2), cvt2(x3) };

            uint4 bv;
            asm volatile("ld.shared.v4.b32 {%0, %1, %2, %3}, [%4];"
                         : "=r"(bv.x), "=r"(bv.y), "=r"(bv.z), "=r"(bv.w)
                         : "r"(bfr + bt + (unsigned)(s * 512)));

            mma16816(acc,     a, bv.x, bv.y);   // n 0-7
            mma16816(acc + 4, a, bv.z, bv.w);   // n 8-15
        }
    }

    asm volatile("cp.async.wait_group 0;" ::: "memory");       // drain before smem reuse

    // ---- ssq reduce across the 4 lanes sharing each row ----
    float2 pa = unpk(ssqa), pb = unpk(ssqb);
    float sa = pa.x + pa.y, sb2 = pb.x + pb.y;
    sa  += __shfl_xor_sync(0xffffffffu, sa, 1);
    sa  += __shfl_xor_sync(0xffffffffu, sa, 2);
    sb2 += __shfl_xor_sync(0xffffffffu, sb2, 1);
    sb2 += __shfl_xor_sync(0xffffffffu, sb2, 2);

    // ---- stash D + ssq into this warp's (now free) x-stage smem ----
    float* dsm = (float*)(sm + warp * XWARP);   // 16 rows x 16 cols
    float* ssm = dsm + 256;
    {
        const int q = lane >> 2, i = lane & 3;
        dsm[q * 16 + 2 * i]            = acc[0];
        dsm[q * 16 + 2 * i + 1]        = acc[1];
        dsm[(q + 8) * 16 + 2 * i]      = acc[2];
        dsm[(q + 8) * 16 + 2 * i + 1]  = acc[3];
        dsm[q * 16 + 8 + 2 * i]        = acc[4];
        dsm[q * 16 + 9 + 2 * i]        = acc[5];
        dsm[(q + 8) * 16 + 8 + 2 * i]  = acc[6];
        dsm[(q + 8) * 16 + 9 + 2 * i]  = acc[7];
        if (i == 0) { ssm[q] = sa; ssm[q + 8] = sb2; }
    }
    __syncwarp();

    // ---- lanes 0-15: one row each -> scale, exp, Sinkhorn(20), store ----
    if (lane < 16) {
        const int row = lane;
        const float scale = rsqrtf(ssm[row] * (1.0f / (float)D) + 1.1920929e-07f);

        float m[16];
#pragma unroll
        for (int j = 0; j < 16; ++j)
            m[j] = __expf(fmaf(scale, dsm[row * 16 + j], bias[j]));

#pragma unroll 4
        for (int it = 0; it < 20; ++it) {
#pragma unroll
            for (int j = 0; j < 4; ++j) {              // column normalize
                float cs = m[j] + m[4 + j] + m[8 + j] + m[12 + j];
                float rc = __fdividef(1.0f, cs + 1e-8f);
                m[j] *= rc; m[4 + j] *= rc; m[8 + j] *= rc; m[12 + j] *= rc;
            }
#pragma unroll
            for (int i = 0; i < 4; ++i) {              // row normalize
                float rs = m[4 * i] + m[4 * i + 1] + m[4 * i + 2] + m[4 * i + 3];
                float rc = __fdividef(1.0f, rs + 1e-8f);
                m[4 * i] *= rc; m[4 * i + 1] *= rc; m[4 * i + 2] *= rc; m[4 * i + 3] *= rc;
            }
        }

        float4* o = (float4*)(out + (row0 + row) * NJ);
        o[0] = make_float4(m[0],  m[1],  m[2],  m[3]);
        o[1] = make_float4(m[4],  m[5],  m[6],  m[7]);
        o[2] = make_float4(m[8],  m[9],  m[10], m[11]);
        o[3] = make_float4(m[12], m[13], m[14], m[15]);
    }
}

extern "C" void kernel_launch(void* const* d_in, const int* in_sizes, int n_in,
                              void* d_out, int out_size)
{
    const float* x     = (const float*)d_in[0];
    const float* W     = (const float*)d_in[1];
    const float* bias  = (const float*)d_in[2];
    const float* alpha = (const float*)d_in[3];
    float* out = (float*)d_out;

    prep_kernel<<<128, 256>>>(W, alpha);

    cudaFuncSetAttribute(rsm_kernel, cudaFuncAttributeMaxDynamicSharedMemorySize, SMEM_B);

    rsm_kernel<<<NBLOCKS, THREADS, SMEM_B>>>(x, bias, out);
}